// round 15
// baseline (speedup 1.0000x reference)
#include <cuda_runtime.h>
#include <math.h>
#include <stdint.h>

#define NS 2048
#define DD 256
#define BB 4
#define KC 32
#define KCP 40
#define NP2 72

// ---- output layout (floats), tuple order:
// est_eigenbasis (B,2,N,D), out (B,2,N,D), Q_ij (B,2,N,N), V_v (1,2,N,D),
// U_v (B,2,N,D), lambda_h (2,D,1)
static const size_t EST_OFF = 0;
static const size_t OUT_OFF = (size_t)BB * 2 * NS * DD;
static const size_t QIJ_OFF = OUT_OFF + (size_t)BB * 2 * NS * DD;
static const size_t VV_OFF  = QIJ_OFF + (size_t)BB * 2 * NS * NS;
static const size_t UV_OFF  = VV_OFF + (size_t)2 * NS * DD;
static const size_t LAM_OFF = UV_OFF + (size_t)BB * 2 * NS * DD;

// ---- scratch (device globals; no allocation allowed)
__device__ float g_ga, g_om, g_s, g_tau2;
__device__ __align__(16) float g_Qr[BB * NS * DD];
__device__ __align__(16) float g_Kr[BB * NS * DD];
__device__ float g_qn[BB * NS];
__device__ float g_kn[BB * NS];

__device__ __forceinline__ float neginf() { return __int_as_float(0xff800000); }

__device__ __forceinline__ uint32_t f2tf(float x) {
    uint32_t r;
    asm("cvt.rna.tf32.f32 %0, %1;" : "=r"(r) : "f"(x));
    return r;
}

__device__ __forceinline__ void mma_tf32(float* d, const uint32_t* a, const uint32_t* b) {
    asm volatile(
        "mma.sync.aligned.m16n8k8.row.col.f32.tf32.tf32.f32 "
        "{%0,%1,%2,%3}, {%4,%5,%6,%7}, {%8,%9}, {%0,%1,%2,%3};"
        : "+f"(d[0]), "+f"(d[1]), "+f"(d[2]), "+f"(d[3])
        : "r"(a[0]), "r"(a[1]), "r"(a[2]), "r"(a[3]), "r"(b[0]), "r"(b[1]));
}

// ============================================================================
// k-PAIRED smem layout for clinear/scores: within each 8-k group, elements
// are stored in order [0,4,1,5,2,6,3,7] so the mma fragment pair (lc, lc+4)
// is adjacent -> one LDS.64 instead of two LDS.32. KCP=40 padding makes the
// paired loads bank-conflict-free (bank = 8*lr + 2*lc mod 32 per half-warp).
// GEMM compute (512 thr, 16 warps 4m x 4n, warp tile 32x32), paired loads.
// ============================================================================
#define GEMM_COMPUTE2(AsB, BsB)                                                \
    _Pragma("unroll")                                                          \
    for (int kk = 0; kk < KC; kk += 8) {                                       \
        uint32_t af[2][4], bf[4][2];                                           \
        _Pragma("unroll")                                                      \
        for (int mt = 0; mt < 2; mt++) {                                       \
            int ab = (wm * 32 + mt * 16 + lr) * KCP + kk + 2 * lc;             \
            uint2 a0 = *(const uint2*)&(AsB)[ab];                              \
            uint2 a1 = *(const uint2*)&(AsB)[ab + 8 * KCP];                    \
            af[mt][0] = a0.x; af[mt][1] = a1.x;                                \
            af[mt][2] = a0.y; af[mt][3] = a1.y;                                \
        }                                                                      \
        _Pragma("unroll")                                                      \
        for (int nt = 0; nt < 4; nt++) {                                       \
            int bb2 = (wn * 32 + nt * 8 + lr) * KCP + kk + 2 * lc;             \
            uint2 b0 = *(const uint2*)&(BsB)[bb2];                             \
            bf[nt][0] = b0.x; bf[nt][1] = b0.y;                                \
        }                                                                      \
        _Pragma("unroll")                                                      \
        for (int mt = 0; mt < 2; mt++)                                         \
            _Pragma("unroll")                                                  \
            for (int nt = 0; nt < 4; nt++)                                     \
                mma_tf32(acc[mt][nt], af[mt], bf[nt]);                         \
    }

// Store 8 k-consecutive floats (reg[0]=k..k+3, reg[1]=k+4..k+7) into the
// PAIRED layout: pairs (v0,v4)(v1,v5)(v2,v6)(v3,v7) at offsets 0,2,4,6.
#define STS_TILE8P(dst, reg)                                                   \
    {                                                                          \
        uint2 u0 = {f2tf((reg)[0].x), f2tf((reg)[1].x)};                       \
        uint2 u1 = {f2tf((reg)[0].y), f2tf((reg)[1].y)};                       \
        uint2 u2 = {f2tf((reg)[0].z), f2tf((reg)[1].z)};                       \
        uint2 u3 = {f2tf((reg)[0].w), f2tf((reg)[1].w)};                       \
        *(uint2*)((dst) + 0) = u0;                                             \
        *(uint2*)((dst) + 2) = u1;                                             \
        *(uint2*)((dst) + 4) = u2;                                             \
        *(uint2*)((dst) + 6) = u3;                                             \
    }

// Linear-layout store (A@V kernel keeps the unpermuted layout)
#define STS_TILE16(dst, reg)                                                   \
    {                                                                          \
        _Pragma("unroll")                                                      \
        for (int j = 0; j < 4; j++) {                                          \
            uint4 u;                                                           \
            u.x = f2tf((reg)[j].x); u.y = f2tf((reg)[j].y);                    \
            u.z = f2tf((reg)[j].z); u.w = f2tf((reg)[j].w);                    \
            *(uint4*)((dst) + 4 * j) = u;                                      \
        }                                                                      \
    }

// ============================================================================
__global__ void k_scalars(const float* __restrict__ lamOm,
                          const float* __restrict__ lamGa,
                          const float* __restrict__ lamC,
                          const float* __restrict__ tau,
                          const float* __restrict__ delta) {
    __shared__ float sga[8], som[8];
    int t = threadIdx.x;
    float c2 = lamC[t] * lamC[t];
    float ga = c2 * (lamGa[t] * lamGa[t] + 1e-5f);
    float om = c2 * (lamOm[t] * lamOm[t] + 1e-5f);
    for (int o = 16; o > 0; o >>= 1) {
        ga += __shfl_down_sync(0xffffffffu, ga, o);
        om += __shfl_down_sync(0xffffffffu, om, o);
    }
    if ((t & 31) == 0) { sga[t >> 5] = ga; som[t >> 5] = om; }
    __syncthreads();
    if (t == 0) {
        float a = 0.f, b = 0.f;
        for (int w = 0; w < 8; w++) { a += sga[w]; b += som[w]; }
        g_ga = a / 256.0f;
        g_om = b / 256.0f;
        g_s = 1.0f / (1.0f + expf(-delta[0]));
        g_tau2 = tau[0] * tau[0];
    }
}

// ============================================================================
// clinear (512 threads): C = Z0.Wa^T + sign*Z1.Wb^T + bias, K=512.
// Prefetch distance 2, one barrier per stage, paired smem layout.
// ============================================================================
#define CL_LOAD(dstA, dstB, s)                                                 \
    {                                                                          \
        const float* Asrc_ = ((s) < 8) ? Z1 : Z0;                              \
        const float* Bsrc_ = ((s) < 8) ? Wb : Wa;                              \
        int col_ = ((s) & 7) * 32 + aK;                                        \
        const float4* pa_ = (const float4*)(Asrc_ + (size_t)(m0 + aRow) * DD + col_); \
        const float4* pb_ = (const float4*)(Bsrc_ + (size_t)(n0 + aRow) * DD + col_); \
        (dstA)[0] = pa_[0]; (dstA)[1] = pa_[1];                                \
        (dstB)[0] = pb_[0]; (dstB)[1] = pb_[1];                                \
    }

#define CL_STAGE(kt, arX, brX, AsB, BsB)                                       \
    {                                                                          \
        STS_TILE8P((AsB) + aRow * KCP + aK, arX);                              \
        STS_TILE8P((BsB) + aRow * KCP + aK, brX);                              \
        __syncthreads();                                                       \
        if ((kt) + 2 < 16) CL_LOAD(arX, brX, (kt) + 2);                        \
        GEMM_COMPUTE2(AsB, BsB);                                               \
        if ((kt) == 7) {                                                       \
            _Pragma("unroll")                                                  \
            for (int mt = 0; mt < 2; mt++)                                     \
                _Pragma("unroll")                                              \
                for (int nt = 0; nt < 4; nt++)                                 \
                    _Pragma("unroll")                                          \
                    for (int q = 0; q < 4; q++) acc[mt][nt][q] *= sign;        \
        }                                                                      \
    }

__global__ __launch_bounds__(512) void k_clinear_tc(
    const float* __restrict__ Z, const float* __restrict__ Wa,
    const float* __restrict__ Wb, float sign, const float* __restrict__ bias,
    float* Cext, long cStride, int destSel, int scaleMode) {
    extern __shared__ uint32_t sm[];
    uint32_t* As0 = sm;
    uint32_t* As1 = sm + 128 * KCP;
    uint32_t* Bs0 = sm + 2 * 128 * KCP;
    uint32_t* Bs1 = sm + 3 * 128 * KCP;
    int b = blockIdx.z;
    const float* Z0 = Z + (size_t)b * 2 * NS * DD;
    const float* Z1 = Z0 + (size_t)NS * DD;
    int n0 = blockIdx.x * 128, m0 = blockIdx.y * 128;
    int t = threadIdx.x, wid = t >> 5, lane = t & 31;
    int wm = wid >> 2, wn = wid & 3, lr = lane >> 2, lc = lane & 3;
    int aRow = t >> 2, aK = (t & 3) * 8;

    float acc[2][4][4] = {};
    float4 ar0[2], br0[2], ar1[2], br1[2];

    CL_LOAD(ar0, br0, 0);
    CL_LOAD(ar1, br1, 1);

    #pragma unroll 1
    for (int kt = 0; kt < 16; kt += 2) {
        CL_STAGE(kt, ar0, br0, As0, Bs0);
        CL_STAGE(kt + 1, ar1, br1, As1, Bs1);
    }

    float* C; long cs;
    if (destSel == 1)      { C = g_Qr; cs = (long)NS * DD; }
    else if (destSel == 2) { C = g_Kr; cs = (long)NS * DD; }
    else                   { C = Cext; cs = cStride; }
    C += (size_t)b * cs;

    float scale = scaleMode ? (1.0f - g_s) : 1.0f;
    #pragma unroll
    for (int mt = 0; mt < 2; mt++) {
        #pragma unroll
        for (int nt = 0; nt < 4; nt++) {
            int col = n0 + wn * 32 + nt * 8 + lc * 2;
            float b0 = bias[col], b1 = bias[col + 1];
            int r0 = m0 + wm * 32 + mt * 16 + lr;
            float2 o0, o1;
            o0.x = (acc[mt][nt][0] + b0) * scale;
            o0.y = (acc[mt][nt][1] + b1) * scale;
            o1.x = (acc[mt][nt][2] + b0) * scale;
            o1.y = (acc[mt][nt][3] + b1) * scale;
            *(float2*)(C + (size_t)r0 * DD + col) = o0;
            *(float2*)(C + (size_t)(r0 + 8) * DD + col) = o1;
        }
    }
}

// ============================================================================
// Row norms, merged: blockIdx.y = 0 -> Q, 1 -> K
// ============================================================================
__global__ void k_norms2() {
    int which = blockIdx.y;
    const float* X = which ? g_Kr : g_Qr;
    float* out = which ? g_kn : g_qn;
    int warp = threadIdx.x >> 5, lane = threadIdx.x & 31;
    int row = blockIdx.x * 8 + warp;
    const float* p = X + (size_t)row * DD;
    float s = 0.f;
    #pragma unroll
    for (int l = 0; l < 8; l++) { float v = p[lane + l * 32]; s += v * v; }
    for (int o = 16; o > 0; o >>= 1) s += __shfl_down_sync(0xffffffffu, s, o);
    if (lane == 0) out[row] = s;
}

// ============================================================================
// Scores (512 threads): tile 128x128, bx<=by only. Prefetch 2, one sync,
// paired smem layout.
// ============================================================================
#define SC_LOAD(dstA, dstB, s)                                                 \
    {                                                                          \
        int col_ = (s) * 32 + aK;                                              \
        const float4* pa_ = (const float4*)(Q + (size_t)(i0 + aRow) * DD + col_); \
        const float4* pb_ = (const float4*)(K + (size_t)(j0 + aRow) * DD + col_); \
        (dstA)[0] = pa_[0]; (dstA)[1] = pa_[1];                                \
        (dstB)[0] = pb_[0]; (dstB)[1] = pb_[1];                                \
    }

#define SC_STAGE(kt, arX, brX, AsB, BsB)                                       \
    {                                                                          \
        STS_TILE8P((AsB) + aRow * KCP + aK, arX);                              \
        STS_TILE8P((BsB) + aRow * KCP + aK, brX);                              \
        __syncthreads();                                                       \
        if ((kt) + 2 < 8) SC_LOAD(arX, brX, (kt) + 2);                         \
        GEMM_COMPUTE2(AsB, BsB);                                               \
    }

__global__ __launch_bounds__(512) void k_scores_tc(float* __restrict__ Aout) {
    if (blockIdx.x > blockIdx.y) return;
    extern __shared__ uint32_t sm[];
    uint32_t* As0 = sm;
    uint32_t* As1 = sm + 128 * KCP;
    uint32_t* Bs0 = sm + 2 * 128 * KCP;
    uint32_t* Bs1 = sm + 3 * 128 * KCP;
    int b = blockIdx.z;
    int j0 = blockIdx.x * 128, i0 = blockIdx.y * 128;
    float* C = Aout + (size_t)b * 2 * NS * NS;
    const float* Q = g_Qr + (size_t)b * NS * DD;
    const float* K = g_Kr + (size_t)b * NS * DD;
    int t = threadIdx.x, wid = t >> 5, lane = t & 31;
    int wm = wid >> 2, wn = wid & 3, lr = lane >> 2, lc = lane & 3;
    int aRow = t >> 2, aK = (t & 3) * 8;

    float acc[2][4][4] = {};
    float4 ar0[2], br0[2], ar1[2], br1[2];

    SC_LOAD(ar0, br0, 0);
    SC_LOAD(ar1, br1, 1);

    #pragma unroll 1
    for (int kt = 0; kt < 8; kt += 2) {
        SC_STAGE(kt, ar0, br0, As0, Bs0);
        SC_STAGE(kt + 1, ar1, br1, As1, Bs1);
    }

    float tau2 = g_tau2, ga = g_ga, om = g_om;
    #pragma unroll
    for (int mt = 0; mt < 2; mt++) {
        #pragma unroll
        for (int half = 0; half < 2; half++) {
            int gi = i0 + wm * 32 + mt * 16 + lr + half * 8;
            float qn = g_qn[b * NS + gi];
            float* crow = C + (size_t)gi * NS;
            #pragma unroll
            for (int nt = 0; nt < 4; nt++) {
                int gj = j0 + wn * 32 + nt * 8 + lc * 2;
                float a0 = acc[mt][nt][half * 2 + 0];
                float a1 = acc[mt][nt][half * 2 + 1];
                if (gj + 1 <= gi) {
                    float2 o;
                    float r0 = qn + g_kn[b * NS + gj] - 2.0f * a0;
                    float r1 = qn + g_kn[b * NS + gj + 1] - 2.0f * a1;
                    o.x = -tau2 * __logf(ga + om * (0.01f * (float)(gi - gj)) + r0);
                    o.y = -tau2 * __logf(ga + om * (0.01f * (float)(gi - gj - 1)) + r1);
                    *(float2*)(crow + gj) = o;
                } else if (gj <= gi) {
                    float r0 = qn + g_kn[b * NS + gj] - 2.0f * a0;
                    crow[gj] = -tau2 * __logf(ga + om * (0.01f * (float)(gi - gj)) + r0);
                }
            }
        }
    }
}

// ============================================================================
// Row softmax (512 threads): reads only j<=i, writes full row.
// ============================================================================
__global__ __launch_bounds__(512) void k_softmax(float* __restrict__ A) {
    __shared__ float buf[NS];
    __shared__ float red[16];
    __shared__ float red2[16];
    int r = blockIdx.x;
    int b = r >> 11, i = r & 2047;
    float* row = A + (size_t)b * 2 * NS * NS + (size_t)i * NS;
    int t = threadIdx.x;
    int L = i + 1;

    float m = neginf();
    #pragma unroll
    for (int l = 0; l < 4; l++) {
        int idx = t + l * 512;
        float v = (idx < L) ? row[idx] : neginf();
        buf[idx] = v;
        m = fmaxf(m, v);
    }
    for (int o = 16; o > 0; o >>= 1) m = fmaxf(m, __shfl_xor_sync(0xffffffffu, m, o));
    if ((t & 31) == 0) red[t >> 5] = m;
    __syncthreads();
    float M = red[0];
    #pragma unroll
    for (int w = 1; w < 16; w++) M = fmaxf(M, red[w]);

    float s = 0.f;
    #pragma unroll
    for (int l = 0; l < 4; l++) {
        int idx = t + l * 512;
        float e = (idx < L) ? __expf(buf[idx] - M) : 0.0f;
        buf[idx] = e;
        s += e;
    }
    for (int o = 16; o > 0; o >>= 1) s += __shfl_xor_sync(0xffffffffu, s, o);
    if ((t & 31) == 0) red2[t >> 5] = s;
    __syncthreads();
    float S = 0.f;
    #pragma unroll
    for (int w = 0; w < 16; w++) S += red2[w];
    float inv = 1.0f / S;
    #pragma unroll
    for (int l = 0; l < 4; l++) {
        int idx = t + l * 512;
        row[idx] = buf[idx] * inv;
    }
}

// ============================================================================
// est_real = (1-s)*V_r + s*(A @ V_r), paired-triangular; one sync per stage.
// (Linear smem layout retained here as control.)
// ============================================================================
__global__ __launch_bounds__(256) void k_av_est_tc(const float* __restrict__ Aout,
                                                   const float* __restrict__ Uv,
                                                   float* __restrict__ est) {
    extern __shared__ uint32_t sm[];
    uint32_t* As0 = sm;
    uint32_t* As1 = sm + 128 * KCP;
    uint32_t* Vs0 = sm + 2 * 128 * KCP;
    uint32_t* Vs1 = Vs0 + 32 * NP2;
    int b = blockIdx.z;
    int n0 = blockIdx.x * 64;
    int p = blockIdx.y;
    const float* A = Aout + (size_t)b * 2 * NS * NS;
    const float* V = Uv + (size_t)b * 2 * NS * DD;
    int t = threadIdx.x, wid = t >> 5, lane = t & 31;
    int wm = wid >> 1, wn = wid & 1, lr = lane >> 2, lc = lane & 3;
    int aRow = t >> 1, aK = (t & 1) * 16;
    int vRow = t >> 3, vCol = (t & 7) * 8;
    float s = g_s, oms = 1.0f - s;
    float* E = est + (size_t)b * 2 * NS * DD;

    #pragma unroll 1
    for (int hp = 0; hp < 2; hp++) {
        int tile = hp ? p : (15 - p);
        int i0 = tile * 128;
        int S = 4 * (tile + 1);

        float acc[2][4][4] = {};
        float4 ar[4], vr[2];
        {
            const float4* pa = (const float4*)(A + (size_t)(i0 + aRow) * NS + aK);
            const float4* pv = (const float4*)(V + (size_t)vRow * DD + n0 + vCol);
            #pragma unroll
            for (int j = 0; j < 4; j++) ar[j] = pa[j];
            vr[0] = pv[0]; vr[1] = pv[1];
        }
        __syncthreads();
        #pragma unroll 1
        for (int kt = 0; kt < S; kt++) {
            uint32_t* AsB = (kt & 1) ? As1 : As0;
            uint32_t* VsB = (kt & 1) ? Vs1 : Vs0;
            STS_TILE16(AsB + aRow * KCP + aK, ar);
            {
                uint32_t* dv = VsB + vRow * NP2 + vCol;
                #pragma unroll
                for (int j = 0; j < 2; j++) {
                    uint4 u;
                    u.x = f2tf(vr[j].x); u.y = f2tf(vr[j].y);
                    u.z = f2tf(vr[j].z); u.w = f2tf(vr[j].w);
                    *(uint4*)(dv + 4 * j) = u;
                }
            }
            __syncthreads();
            if (kt + 1 < S) {
                int k0 = (kt + 1) * 32;
                const float4* pa = (const float4*)(A + (size_t)(i0 + aRow) * NS + k0 + aK);
                const float4* pv = (const float4*)(V + (size_t)(k0 + vRow) * DD + n0 + vCol);
                #pragma unroll
                for (int j = 0; j < 4; j++) ar[j] = pa[j];
                vr[0] = pv[0]; vr[1] = pv[1];
            }
            #pragma unroll
            for (int kk = 0; kk < KC; kk += 8) {
                uint32_t af[2][4], bf[4][2];
                #pragma unroll
                for (int mt = 0; mt < 2; mt++) {
                    int ab = (wm * 32 + mt * 16 + lr) * KCP + kk + lc;
                    af[mt][0] = AsB[ab];
                    af[mt][1] = AsB[ab + 8 * KCP];
                    af[mt][2] = AsB[ab + 4];
                    af[mt][3] = AsB[ab + 8 * KCP + 4];
                }
                #pragma unroll
                for (int nt = 0; nt < 4; nt++) {
                    int nb = wn * 32 + nt * 8 + lr;
                    bf[nt][0] = VsB[(kk + lc) * NP2 + nb];
                    bf[nt][1] = VsB[(kk + lc + 4) * NP2 + nb];
                }
                #pragma unroll
                for (int mt = 0; mt < 2; mt++)
                    #pragma unroll
                    for (int nt = 0; nt < 4; nt++)
                        mma_tf32(acc[mt][nt], af[mt], bf[nt]);
            }
        }
        __syncthreads();

        #pragma unroll
        for (int mt = 0; mt < 2; mt++) {
            #pragma unroll
            for (int half = 0; half < 2; half++) {
                int row = i0 + wm * 32 + mt * 16 + lr + half * 8;
                #pragma unroll
                for (int nt = 0; nt < 4; nt++) {
                    int col = n0 + wn * 32 + nt * 8 + lc * 2;
                    float2 vv = *(const float2*)(V + (size_t)row * DD + col);
                    float2 o;
                    o.x = oms * vv.x + s * acc[mt][nt][half * 2 + 0];
                    o.y = oms * vv.y + s * acc[mt][nt][half * 2 + 1];
                    *(float2*)(E + (size_t)row * DD + col) = o;
                }
            }
        }
    }
}

// ============================================================================
// One merged fill kernel for ALL constant output regions.
// ============================================================================
#define F4_ONES 131072UL
#define F4_VVI  131072UL
#define F4_UVI  (4UL * 131072UL)
#define F4_QIJ  (4UL * 1048576UL)
#define F4_LAM  128UL
#define F4_TOT  (F4_ONES + F4_VVI + F4_UVI + F4_QIJ + F4_LAM)

__global__ void k_fill_all(float* __restrict__ out) {
    const float4 Z = {0.f, 0.f, 0.f, 0.f};
    const float4 O = {1.f, 1.f, 1.f, 1.f};
    size_t i = (size_t)blockIdx.x * blockDim.x + threadIdx.x;
    size_t stride = (size_t)gridDim.x * blockDim.x;
    for (; i < F4_TOT; i += stride) {
        size_t j = i;
        if (j < F4_ONES) {
            ((float4*)(out + VV_OFF))[j] = O;
            continue;
        }
        j -= F4_ONES;
        float4* dst;
        if (j < F4_VVI) {
            dst = (float4*)(out + VV_OFF + (size_t)NS * DD) + j;
        } else {
            j -= F4_VVI;
            if (j < F4_UVI) {
                size_t b = j >> 17, o = j & 131071UL;
                dst = (float4*)(out + UV_OFF + (2 * b + 1) * (size_t)NS * DD) + o;
            } else {
                j -= F4_UVI;
                if (j < F4_QIJ) {
                    size_t b = j >> 20, o = j & 1048575UL;
                    dst = (float4*)(out + QIJ_OFF + (2 * b + 1) * (size_t)NS * NS) + o;
                } else {
                    j -= F4_QIJ;
                    dst = (float4*)(out + LAM_OFF) + j;
                }
            }
        }
        *dst = Z;
    }
}

// ============================================================================
extern "C" void kernel_launch(void* const* d_in, const int* in_sizes, int n_in,
                              void* d_out, int out_size) {
    const float* Zq    = (const float*)d_in[0];
    const float* Zk    = (const float*)d_in[1];
    const float* Zv    = (const float*)d_in[2];
    const float* Wq    = (const float*)d_in[4];
    const float* bq    = (const float*)d_in[5];
    const float* Wk    = (const float*)d_in[6];
    const float* bk    = (const float*)d_in[7];
    const float* Wv    = (const float*)d_in[8];
    const float* bv    = (const float*)d_in[9];
    const float* Wp    = (const float*)d_in[10];
    const float* bp    = (const float*)d_in[11];
    const float* lamOm = (const float*)d_in[13];
    const float* lamGa = (const float*)d_in[14];
    const float* tau   = (const float*)d_in[15];
    const float* delta = (const float*)d_in[16];
    const float* lamC  = (const float*)d_in[17];

    float* out = (float*)d_out;
    const long DxD = (long)DD * DD;
    const long cs2 = (long)2 * NS * DD;

    const int SMEM_GEMM = 4 * 128 * KCP * 4;                    // 81920
    const int SMEM_AV   = (2 * 128 * KCP + 2 * 32 * NP2) * 4;   // 59392
    cudaFuncSetAttribute(k_clinear_tc, cudaFuncAttributeMaxDynamicSharedMemorySize, SMEM_GEMM);
    cudaFuncSetAttribute(k_scores_tc,  cudaFuncAttributeMaxDynamicSharedMemorySize, SMEM_GEMM);
    cudaFuncSetAttribute(k_av_est_tc,  cudaFuncAttributeMaxDynamicSharedMemorySize, SMEM_AV);

    k_scalars<<<1, 256>>>(lamOm, lamGa, lamC, tau, delta);

    // merged fills (independent; fire early)
    k_fill_all<<<2368, 256>>>(out);

    dim3 gl(DD / 128, NS / 128, BB);  // (2, 16, 4)
    k_clinear_tc<<<gl, 512, SMEM_GEMM>>>(Zq, Wq, Wq + DxD, -1.0f, bq, nullptr, 0, 1, 0);
    k_clinear_tc<<<gl, 512, SMEM_GEMM>>>(Zk, Wk, Wk + DxD, -1.0f, bk, nullptr, 0, 2, 0);
    k_clinear_tc<<<gl, 512, SMEM_GEMM>>>(Zv, Wv, Wv + DxD, -1.0f, bv, out + UV_OFF, cs2, 0, 0);
    k_clinear_tc<<<gl, 512, SMEM_GEMM>>>(Zv, Wv + DxD, Wv, 1.0f, bv + DD,
                                         out + EST_OFF + (size_t)NS * DD, cs2, 0, 1);

    k_norms2<<<dim3(BB * NS / 8, 2), 256>>>();

    k_scores_tc<<<dim3(NS / 128, NS / 128, BB), 512, SMEM_GEMM>>>(out + QIJ_OFF);
    k_softmax<<<BB * NS, 512>>>(out + QIJ_OFF);

    k_av_est_tc<<<dim3(DD / 64, 8, BB), 256, SMEM_AV>>>(out + QIJ_OFF, out + UV_OFF,
                                                        out + EST_OFF);

    k_clinear_tc<<<gl, 512, SMEM_GEMM>>>(out + EST_OFF, Wp, Wp + DxD, -1.0f, bp,
                                         out + OUT_OFF, cs2, 0, 0);
    k_clinear_tc<<<gl, 512, SMEM_GEMM>>>(out + EST_OFF, Wp + DxD, Wp, 1.0f, bp + DD,
                                         out + OUT_OFF + (size_t)NS * DD, cs2, 0, 0);
}

// round 16
// speedup vs baseline: 1.0462x; 1.0462x over previous
#include <cuda_runtime.h>
#include <math.h>
#include <stdint.h>

#define NS 2048
#define DD 256
#define BB 4
// A@V kernel tiling (unchanged)
#define KC 32
#define KCP 36
#define NP2 72
// clinear/scores tiling: K-stage 64, padded row 68 (68 mod 32 == 4, same
// conflict-free fragment banking as 36)
#define KC2 64
#define KCP2 68

// ---- output layout (floats), tuple order:
// est_eigenbasis (B,2,N,D), out (B,2,N,D), Q_ij (B,2,N,N), V_v (1,2,N,D),
// U_v (B,2,N,D), lambda_h (2,D,1)
static const size_t EST_OFF = 0;
static const size_t OUT_OFF = (size_t)BB * 2 * NS * DD;
static const size_t QIJ_OFF = OUT_OFF + (size_t)BB * 2 * NS * DD;
static const size_t VV_OFF  = QIJ_OFF + (size_t)BB * 2 * NS * NS;
static const size_t UV_OFF  = VV_OFF + (size_t)2 * NS * DD;
static const size_t LAM_OFF = UV_OFF + (size_t)BB * 2 * NS * DD;

// ---- scratch (device globals; no allocation allowed)
__device__ float g_ga, g_om, g_s, g_tau2;
__device__ __align__(16) float g_Qr[BB * NS * DD];
__device__ __align__(16) float g_Kr[BB * NS * DD];
__device__ float g_qn[BB * NS];
__device__ float g_kn[BB * NS];

__device__ __forceinline__ float neginf() { return __int_as_float(0xff800000); }

__device__ __forceinline__ uint32_t f2tf(float x) {
    uint32_t r;
    asm("cvt.rna.tf32.f32 %0, %1;" : "=r"(r) : "f"(x));
    return r;
}

__device__ __forceinline__ void mma_tf32(float* d, const uint32_t* a, const uint32_t* b) {
    asm volatile(
        "mma.sync.aligned.m16n8k8.row.col.f32.tf32.tf32.f32 "
        "{%0,%1,%2,%3}, {%4,%5,%6,%7}, {%8,%9}, {%0,%1,%2,%3};"
        : "+f"(d[0]), "+f"(d[1]), "+f"(d[2]), "+f"(d[3])
        : "r"(a[0]), "r"(a[1]), "r"(a[2]), "r"(a[3]), "r"(b[0]), "r"(b[1]));
}

// 512-thread GEMM fragment compute over a KC2-deep stage: 16 warps (4m x 4n),
// warp tile 32x32. Smem row-major [row][k], KCP2-padded (conflict-free).
#define GEMM_COMPUTE64(AsB, BsB)                                               \
    _Pragma("unroll")                                                          \
    for (int kk = 0; kk < KC2; kk += 8) {                                      \
        uint32_t af[2][4], bf[4][2];                                           \
        _Pragma("unroll")                                                      \
        for (int mt = 0; mt < 2; mt++) {                                       \
            int ab = (wm * 32 + mt * 16 + lr) * KCP2 + kk + lc;                \
            af[mt][0] = (AsB)[ab];                                             \
            af[mt][1] = (AsB)[ab + 8 * KCP2];                                  \
            af[mt][2] = (AsB)[ab + 4];                                         \
            af[mt][3] = (AsB)[ab + 8 * KCP2 + 4];                              \
        }                                                                      \
        _Pragma("unroll")                                                      \
        for (int nt = 0; nt < 4; nt++) {                                       \
            int bb2 = (wn * 32 + nt * 8 + lr) * KCP2 + kk + lc;                \
            bf[nt][0] = (BsB)[bb2];                                            \
            bf[nt][1] = (BsB)[bb2 + 4];                                        \
        }                                                                      \
        _Pragma("unroll")                                                      \
        for (int mt = 0; mt < 2; mt++)                                         \
            _Pragma("unroll")                                                  \
            for (int nt = 0; nt < 4; nt++)                                     \
                mma_tf32(acc[mt][nt], af[mt], bf[nt]);                         \
    }

// Store 8 consecutive floats (2 float4) tf32-rounded at dst, dst+4
#define STS_TILE8(dst, r0v, r1v)                                               \
    {                                                                          \
        uint4 u0, u1;                                                          \
        u0.x = f2tf((r0v).x); u0.y = f2tf((r0v).y);                            \
        u0.z = f2tf((r0v).z); u0.w = f2tf((r0v).w);                            \
        u1.x = f2tf((r1v).x); u1.y = f2tf((r1v).y);                            \
        u1.z = f2tf((r1v).z); u1.w = f2tf((r1v).w);                            \
        *(uint4*)((dst) + 0) = u0;                                             \
        *(uint4*)((dst) + 4) = u1;                                             \
    }

// Linear-layout 16-float store (A@V kernel)
#define STS_TILE16(dst, reg)                                                   \
    {                                                                          \
        _Pragma("unroll")                                                      \
        for (int j = 0; j < 4; j++) {                                          \
            uint4 u;                                                           \
            u.x = f2tf((reg)[j].x); u.y = f2tf((reg)[j].y);                    \
            u.z = f2tf((reg)[j].z); u.w = f2tf((reg)[j].w);                    \
            *(uint4*)((dst) + 4 * j) = u;                                      \
        }                                                                      \
    }

// ============================================================================
__global__ void k_scalars(const float* __restrict__ lamOm,
                          const float* __restrict__ lamGa,
                          const float* __restrict__ lamC,
                          const float* __restrict__ tau,
                          const float* __restrict__ delta) {
    __shared__ float sga[8], som[8];
    int t = threadIdx.x;
    float c2 = lamC[t] * lamC[t];
    float ga = c2 * (lamGa[t] * lamGa[t] + 1e-5f);
    float om = c2 * (lamOm[t] * lamOm[t] + 1e-5f);
    for (int o = 16; o > 0; o >>= 1) {
        ga += __shfl_down_sync(0xffffffffu, ga, o);
        om += __shfl_down_sync(0xffffffffu, om, o);
    }
    if ((t & 31) == 0) { sga[t >> 5] = ga; som[t >> 5] = om; }
    __syncthreads();
    if (t == 0) {
        float a = 0.f, b = 0.f;
        for (int w = 0; w < 8; w++) { a += sga[w]; b += som[w]; }
        g_ga = a / 256.0f;
        g_om = b / 256.0f;
        g_s = 1.0f / (1.0f + expf(-delta[0]));
        g_tau2 = tau[0] * tau[0];
    }
}

// ============================================================================
// clinear (512 threads): C = Z0.Wa^T + sign*Z1.Wb^T + bias, K=512 as 8 stages
// of KC2=64. Stages 0-3 feed (Z1,Wb), acc*=sign after stage 3, 4-7 (Z0,Wa).
// Prefetch distance 1 (stage is 2x longer -> same absolute LDG slack as the
// old distance-2/KC32 scheme), one barrier per stage, no trailing barrier.
// Loader: thread owns row t>>2, cols (t&3)*8 and (t&3)*8+32 (4 float4 LDGs,
// 2x STS_TILE8 each internally conflict-free).
// ============================================================================
#define CL_LOAD(s)                                                             \
    {                                                                          \
        const float* Asrc_ = ((s) < 4) ? Z1 : Z0;                              \
        const float* Bsrc_ = ((s) < 4) ? Wb : Wa;                              \
        int col_ = ((s) & 3) * 64 + aK;                                        \
        const float* pa_ = Asrc_ + (size_t)(m0 + aRow) * DD + col_;            \
        const float* pb_ = Bsrc_ + (size_t)(n0 + aRow) * DD + col_;            \
        ar[0] = *(const float4*)(pa_);                                         \
        ar[1] = *(const float4*)(pa_ + 4);                                     \
        ar[2] = *(const float4*)(pa_ + 32);                                    \
        ar[3] = *(const float4*)(pa_ + 36);                                    \
        br[0] = *(const float4*)(pb_);                                         \
        br[1] = *(const float4*)(pb_ + 4);                                     \
        br[2] = *(const float4*)(pb_ + 32);                                    \
        br[3] = *(const float4*)(pb_ + 36);                                    \
    }

__global__ __launch_bounds__(512) void k_clinear_tc(
    const float* __restrict__ Z, const float* __restrict__ Wa,
    const float* __restrict__ Wb, float sign, const float* __restrict__ bias,
    float* Cext, long cStride, int destSel, int scaleMode) {
    extern __shared__ uint32_t sm[];
    uint32_t* As0 = sm;
    uint32_t* As1 = sm + 128 * KCP2;
    uint32_t* Bs0 = sm + 2 * 128 * KCP2;
    uint32_t* Bs1 = sm + 3 * 128 * KCP2;
    int b = blockIdx.z;
    const float* Z0 = Z + (size_t)b * 2 * NS * DD;
    const float* Z1 = Z0 + (size_t)NS * DD;
    int n0 = blockIdx.x * 128, m0 = blockIdx.y * 128;
    int t = threadIdx.x, wid = t >> 5, lane = t & 31;
    int wm = wid >> 2, wn = wid & 3, lr = lane >> 2, lc = lane & 3;
    int aRow = t >> 2, aK = (t & 3) * 8;

    float acc[2][4][4] = {};
    float4 ar[4], br[4];

    CL_LOAD(0);

    #pragma unroll 1
    for (int kt = 0; kt < 8; kt++) {
        uint32_t* AsB = (kt & 1) ? As1 : As0;
        uint32_t* BsB = (kt & 1) ? Bs1 : Bs0;
        uint32_t* da = AsB + aRow * KCP2 + aK;
        uint32_t* db = BsB + aRow * KCP2 + aK;
        STS_TILE8(da, ar[0], ar[1]);
        STS_TILE8(da + 32, ar[2], ar[3]);
        STS_TILE8(db, br[0], br[1]);
        STS_TILE8(db + 32, br[2], br[3]);
        __syncthreads();
        if (kt + 1 < 8) CL_LOAD(kt + 1);
        GEMM_COMPUTE64(AsB, BsB);
        if (kt == 3) {
            #pragma unroll
            for (int mt = 0; mt < 2; mt++)
                #pragma unroll
                for (int nt = 0; nt < 4; nt++)
                    #pragma unroll
                    for (int q = 0; q < 4; q++) acc[mt][nt][q] *= sign;
        }
    }

    float* C; long cs;
    if (destSel == 1)      { C = g_Qr; cs = (long)NS * DD; }
    else if (destSel == 2) { C = g_Kr; cs = (long)NS * DD; }
    else                   { C = Cext; cs = cStride; }
    C += (size_t)b * cs;

    float scale = scaleMode ? (1.0f - g_s) : 1.0f;
    #pragma unroll
    for (int mt = 0; mt < 2; mt++) {
        #pragma unroll
        for (int nt = 0; nt < 4; nt++) {
            int col = n0 + wn * 32 + nt * 8 + lc * 2;
            float b0 = bias[col], b1 = bias[col + 1];
            int r0 = m0 + wm * 32 + mt * 16 + lr;
            float2 o0, o1;
            o0.x = (acc[mt][nt][0] + b0) * scale;
            o0.y = (acc[mt][nt][1] + b1) * scale;
            o1.x = (acc[mt][nt][2] + b0) * scale;
            o1.y = (acc[mt][nt][3] + b1) * scale;
            *(float2*)(C + (size_t)r0 * DD + col) = o0;
            *(float2*)(C + (size_t)(r0 + 8) * DD + col) = o1;
        }
    }
}

// ============================================================================
// Row norms, merged: blockIdx.y = 0 -> Q, 1 -> K
// ============================================================================
__global__ void k_norms2() {
    int which = blockIdx.y;
    const float* X = which ? g_Kr : g_Qr;
    float* out = which ? g_kn : g_qn;
    int warp = threadIdx.x >> 5, lane = threadIdx.x & 31;
    int row = blockIdx.x * 8 + warp;
    const float* p = X + (size_t)row * DD;
    float s = 0.f;
    #pragma unroll
    for (int l = 0; l < 8; l++) { float v = p[lane + l * 32]; s += v * v; }
    for (int o = 16; o > 0; o >>= 1) s += __shfl_down_sync(0xffffffffu, s, o);
    if (lane == 0) out[row] = s;
}

// ============================================================================
// Scores (512 threads): tile 128x128, bx<=by only. 4 stages of KC2=64,
// prefetch distance 1, one barrier per stage.
// ============================================================================
#define SC_LOAD(s)                                                             \
    {                                                                          \
        int col_ = (s) * 64 + aK;                                              \
        const float* pa_ = Q + (size_t)(i0 + aRow) * DD + col_;                \
        const float* pb_ = K + (size_t)(j0 + aRow) * DD + col_;                \
        ar[0] = *(const float4*)(pa_);                                         \
        ar[1] = *(const float4*)(pa_ + 4);                                     \
        ar[2] = *(const float4*)(pa_ + 32);                                    \
        ar[3] = *(const float4*)(pa_ + 36);                                    \
        br[0] = *(const float4*)(pb_);                                         \
        br[1] = *(const float4*)(pb_ + 4);                                     \
        br[2] = *(const float4*)(pb_ + 32);                                    \
        br[3] = *(const float4*)(pb_ + 36);                                    \
    }

__global__ __launch_bounds__(512) void k_scores_tc(float* __restrict__ Aout) {
    if (blockIdx.x > blockIdx.y) return;
    extern __shared__ uint32_t sm[];
    uint32_t* As0 = sm;
    uint32_t* As1 = sm + 128 * KCP2;
    uint32_t* Bs0 = sm + 2 * 128 * KCP2;
    uint32_t* Bs1 = sm + 3 * 128 * KCP2;
    int b = blockIdx.z;
    int j0 = blockIdx.x * 128, i0 = blockIdx.y * 128;
    float* C = Aout + (size_t)b * 2 * NS * NS;
    const float* Q = g_Qr + (size_t)b * NS * DD;
    const float* K = g_Kr + (size_t)b * NS * DD;
    int t = threadIdx.x, wid = t >> 5, lane = t & 31;
    int wm = wid >> 2, wn = wid & 3, lr = lane >> 2, lc = lane & 3;
    int aRow = t >> 2, aK = (t & 3) * 8;

    float acc[2][4][4] = {};
    float4 ar[4], br[4];

    SC_LOAD(0);

    #pragma unroll 1
    for (int kt = 0; kt < 4; kt++) {
        uint32_t* AsB = (kt & 1) ? As1 : As0;
        uint32_t* BsB = (kt & 1) ? Bs1 : Bs0;
        uint32_t* da = AsB + aRow * KCP2 + aK;
        uint32_t* db = BsB + aRow * KCP2 + aK;
        STS_TILE8(da, ar[0], ar[1]);
        STS_TILE8(da + 32, ar[2], ar[3]);
        STS_TILE8(db, br[0], br[1]);
        STS_TILE8(db + 32, br[2], br[3]);
        __syncthreads();
        if (kt + 1 < 4) SC_LOAD(kt + 1);
        GEMM_COMPUTE64(AsB, BsB);
    }

    float tau2 = g_tau2, ga = g_ga, om = g_om;
    #pragma unroll
    for (int mt = 0; mt < 2; mt++) {
        #pragma unroll
        for (int half = 0; half < 2; half++) {
            int gi = i0 + wm * 32 + mt * 16 + lr + half * 8;
            float qn = g_qn[b * NS + gi];
            float* crow = C + (size_t)gi * NS;
            #pragma unroll
            for (int nt = 0; nt < 4; nt++) {
                int gj = j0 + wn * 32 + nt * 8 + lc * 2;
                float a0 = acc[mt][nt][half * 2 + 0];
                float a1 = acc[mt][nt][half * 2 + 1];
                if (gj + 1 <= gi) {
                    float2 o;
                    float r0 = qn + g_kn[b * NS + gj] - 2.0f * a0;
                    float r1 = qn + g_kn[b * NS + gj + 1] - 2.0f * a1;
                    o.x = -tau2 * __logf(ga + om * (0.01f * (float)(gi - gj)) + r0);
                    o.y = -tau2 * __logf(ga + om * (0.01f * (float)(gi - gj - 1)) + r1);
                    *(float2*)(crow + gj) = o;
                } else if (gj <= gi) {
                    float r0 = qn + g_kn[b * NS + gj] - 2.0f * a0;
                    crow[gj] = -tau2 * __logf(ga + om * (0.01f * (float)(gi - gj)) + r0);
                }
            }
        }
    }
}

// ============================================================================
// Row softmax (512 threads): reads only j<=i, writes full row.
// ============================================================================
__global__ __launch_bounds__(512) void k_softmax(float* __restrict__ A) {
    __shared__ float buf[NS];
    __shared__ float red[16];
    __shared__ float red2[16];
    int r = blockIdx.x;
    int b = r >> 11, i = r & 2047;
    float* row = A + (size_t)b * 2 * NS * NS + (size_t)i * NS;
    int t = threadIdx.x;
    int L = i + 1;

    float m = neginf();
    #pragma unroll
    for (int l = 0; l < 4; l++) {
        int idx = t + l * 512;
        float v = (idx < L) ? row[idx] : neginf();
        buf[idx] = v;
        m = fmaxf(m, v);
    }
    for (int o = 16; o > 0; o >>= 1) m = fmaxf(m, __shfl_xor_sync(0xffffffffu, m, o));
    if ((t & 31) == 0) red[t >> 5] = m;
    __syncthreads();
    float M = red[0];
    #pragma unroll
    for (int w = 1; w < 16; w++) M = fmaxf(M, red[w]);

    float s = 0.f;
    #pragma unroll
    for (int l = 0; l < 4; l++) {
        int idx = t + l * 512;
        float e = (idx < L) ? __expf(buf[idx] - M) : 0.0f;
        buf[idx] = e;
        s += e;
    }
    for (int o = 16; o > 0; o >>= 1) s += __shfl_xor_sync(0xffffffffu, s, o);
    if ((t & 31) == 0) red2[t >> 5] = s;
    __syncthreads();
    float S = 0.f;
    #pragma unroll
    for (int w = 0; w < 16; w++) S += red2[w];
    float inv = 1.0f / S;
    #pragma unroll
    for (int l = 0; l < 4; l++) {
        int idx = t + l * 512;
        row[idx] = buf[idx] * inv;
    }
}

// ============================================================================
// est_real = (1-s)*V_r + s*(A @ V_r), paired-triangular; one sync per stage.
// (KC=32 / KCP=36 linear layout, unchanged from round 14.)
// ============================================================================
__global__ __launch_bounds__(256) void k_av_est_tc(const float* __restrict__ Aout,
                                                   const float* __restrict__ Uv,
                                                   float* __restrict__ est) {
    extern __shared__ uint32_t sm[];
    uint32_t* As0 = sm;
    uint32_t* As1 = sm + 128 * KCP;
    uint32_t* Vs0 = sm + 2 * 128 * KCP;
    uint32_t* Vs1 = Vs0 + 32 * NP2;
    int b = blockIdx.z;
    int n0 = blockIdx.x * 64;
    int p = blockIdx.y;
    const float* A = Aout + (size_t)b * 2 * NS * NS;
    const float* V = Uv + (size_t)b * 2 * NS * DD;
    int t = threadIdx.x, wid = t >> 5, lane = t & 31;
    int wm = wid >> 1, wn = wid & 1, lr = lane >> 2, lc = lane & 3;
    int aRow = t >> 1, aK = (t & 1) * 16;
    int vRow = t >> 3, vCol = (t & 7) * 8;
    float s = g_s, oms = 1.0f - s;
    float* E = est + (size_t)b * 2 * NS * DD;

    #pragma unroll 1
    for (int hp = 0; hp < 2; hp++) {
        int tile = hp ? p : (15 - p);
        int i0 = tile * 128;
        int S = 4 * (tile + 1);

        float acc[2][4][4] = {};
        float4 ar[4], vr[2];
        {
            const float4* pa = (const float4*)(A + (size_t)(i0 + aRow) * NS + aK);
            const float4* pv = (const float4*)(V + (size_t)vRow * DD + n0 + vCol);
            #pragma unroll
            for (int j = 0; j < 4; j++) ar[j] = pa[j];
            vr[0] = pv[0]; vr[1] = pv[1];
        }
        __syncthreads();
        #pragma unroll 1
        for (int kt = 0; kt < S; kt++) {
            uint32_t* AsB = (kt & 1) ? As1 : As0;
            uint32_t* VsB = (kt & 1) ? Vs1 : Vs0;
            STS_TILE16(AsB + aRow * KCP + aK, ar);
            {
                uint32_t* dv = VsB + vRow * NP2 + vCol;
                #pragma unroll
                for (int j = 0; j < 2; j++) {
                    uint4 u;
                    u.x = f2tf(vr[j].x); u.y = f2tf(vr[j].y);
                    u.z = f2tf(vr[j].z); u.w = f2tf(vr[j].w);
                    *(uint4*)(dv + 4 * j) = u;
                }
            }
            __syncthreads();
            if (kt + 1 < S) {
                int k0 = (kt + 1) * 32;
                const float4* pa = (const float4*)(A + (size_t)(i0 + aRow) * NS + k0 + aK);
                const float4* pv = (const float4*)(V + (size_t)(k0 + vRow) * DD + n0 + vCol);
                #pragma unroll
                for (int j = 0; j < 4; j++) ar[j] = pa[j];
                vr[0] = pv[0]; vr[1] = pv[1];
            }
            #pragma unroll
            for (int kk = 0; kk < KC; kk += 8) {
                uint32_t af[2][4], bf[4][2];
                #pragma unroll
                for (int mt = 0; mt < 2; mt++) {
                    int ab = (wm * 32 + mt * 16 + lr) * KCP + kk + lc;
                    af[mt][0] = AsB[ab];
                    af[mt][1] = AsB[ab + 8 * KCP];
                    af[mt][2] = AsB[ab + 4];
                    af[mt][3] = AsB[ab + 8 * KCP + 4];
                }
                #pragma unroll
                for (int nt = 0; nt < 4; nt++) {
                    int nb = wn * 32 + nt * 8 + lr;
                    bf[nt][0] = VsB[(kk + lc) * NP2 + nb];
                    bf[nt][1] = VsB[(kk + lc + 4) * NP2 + nb];
                }
                #pragma unroll
                for (int mt = 0; mt < 2; mt++)
                    #pragma unroll
                    for (int nt = 0; nt < 4; nt++)
                        mma_tf32(acc[mt][nt], af[mt], bf[nt]);
            }
        }
        __syncthreads();

        #pragma unroll
        for (int mt = 0; mt < 2; mt++) {
            #pragma unroll
            for (int half = 0; half < 2; half++) {
                int row = i0 + wm * 32 + mt * 16 + lr + half * 8;
                #pragma unroll
                for (int nt = 0; nt < 4; nt++) {
                    int col = n0 + wn * 32 + nt * 8 + lc * 2;
                    float2 vv = *(const float2*)(V + (size_t)row * DD + col);
                    float2 o;
                    o.x = oms * vv.x + s * acc[mt][nt][half * 2 + 0];
                    o.y = oms * vv.y + s * acc[mt][nt][half * 2 + 1];
                    *(float2*)(E + (size_t)row * DD + col) = o;
                }
            }
        }
    }
}

// ============================================================================
// One merged fill kernel for ALL constant output regions.
// ============================================================================
#define F4_ONES 131072UL
#define F4_VVI  131072UL
#define F4_UVI  (4UL * 131072UL)
#define F4_QIJ  (4UL * 1048576UL)
#define F4_LAM  128UL
#define F4_TOT  (F4_ONES + F4_VVI + F4_UVI + F4_QIJ + F4_LAM)

__global__ void k_fill_all(float* __restrict__ out) {
    const float4 Z = {0.f, 0.f, 0.f, 0.f};
    const float4 O = {1.f, 1.f, 1.f, 1.f};
    size_t i = (size_t)blockIdx.x * blockDim.x + threadIdx.x;
    size_t stride = (size_t)gridDim.x * blockDim.x;
    for (; i < F4_TOT; i += stride) {
        size_t j = i;
        if (j < F4_ONES) {
            ((float4*)(out + VV_OFF))[j] = O;
            continue;
        }
        j -= F4_ONES;
        float4* dst;
        if (j < F4_VVI) {
            dst = (float4*)(out + VV_OFF + (size_t)NS * DD) + j;
        } else {
            j -= F4_VVI;
            if (j < F4_UVI) {
                size_t b = j >> 17, o = j & 131071UL;
                dst = (float4*)(out + UV_OFF + (2 * b + 1) * (size_t)NS * DD) + o;
            } else {
                j -= F4_UVI;
                if (j < F4_QIJ) {
                    size_t b = j >> 20, o = j & 1048575UL;
                    dst = (float4*)(out + QIJ_OFF + (2 * b + 1) * (size_t)NS * NS) + o;
                } else {
                    j -= F4_QIJ;
                    dst = (float4*)(out + LAM_OFF) + j;
                }
            }
        }
        *dst = Z;
    }
}

// ============================================================================
extern "C" void kernel_launch(void* const* d_in, const int* in_sizes, int n_in,
                              void* d_out, int out_size) {
    const float* Zq    = (const float*)d_in[0];
    const float* Zk    = (const float*)d_in[1];
    const float* Zv    = (const float*)d_in[2];
    const float* Wq    = (const float*)d_in[4];
    const float* bq    = (const float*)d_in[5];
    const float* Wk    = (const float*)d_in[6];
    const float* bk    = (const float*)d_in[7];
    const float* Wv    = (const float*)d_in[8];
    const float* bv    = (const float*)d_in[9];
    const float* Wp    = (const float*)d_in[10];
    const float* bp    = (const float*)d_in[11];
    const float* lamOm = (const float*)d_in[13];
    const float* lamGa = (const float*)d_in[14];
    const float* tau   = (const float*)d_in[15];
    const float* delta = (const float*)d_in[16];
    const float* lamC  = (const float*)d_in[17];

    float* out = (float*)d_out;
    const long DxD = (long)DD * DD;
    const long cs2 = (long)2 * NS * DD;

    const int SMEM_GEMM = 4 * 128 * KCP2 * 4;                   // 139264
    const int SMEM_AV   = (2 * 128 * KCP + 2 * 32 * NP2) * 4;   // 55296
    cudaFuncSetAttribute(k_clinear_tc, cudaFuncAttributeMaxDynamicSharedMemorySize, SMEM_GEMM);
    cudaFuncSetAttribute(k_scores_tc,  cudaFuncAttributeMaxDynamicSharedMemorySize, SMEM_GEMM);
    cudaFuncSetAttribute(k_av_est_tc,  cudaFuncAttributeMaxDynamicSharedMemorySize, SMEM_AV);

    k_scalars<<<1, 256>>>(lamOm, lamGa, lamC, tau, delta);

    // merged fills (independent; fire early)
    k_fill_all<<<2368, 256>>>(out);

    dim3 gl(DD / 128, NS / 128, BB);  // (2, 16, 4)
    k_clinear_tc<<<gl, 512, SMEM_GEMM>>>(Zq, Wq, Wq + DxD, -1.0f, bq, nullptr, 0, 1, 0);
    k_clinear_tc<<<gl, 512, SMEM_GEMM>>>(Zk, Wk, Wk + DxD, -1.0f, bk, nullptr, 0, 2, 0);
    k_clinear_tc<<<gl, 512, SMEM_GEMM>>>(Zv, Wv, Wv + DxD, -1.0f, bv, out + UV_OFF, cs2, 0, 0);
    k_clinear_tc<<<gl, 512, SMEM_GEMM>>>(Zv, Wv + DxD, Wv, 1.0f, bv + DD,
                                         out + EST_OFF + (size_t)NS * DD, cs2, 0, 1);

    k_norms2<<<dim3(BB * NS / 8, 2), 256>>>();

    k_scores_tc<<<dim3(NS / 128, NS / 128, BB), 512, SMEM_GEMM>>>(out + QIJ_OFF);
    k_softmax<<<BB * NS, 512>>>(out + QIJ_OFF);

    k_av_est_tc<<<dim3(DD / 64, 8, BB), 256, SMEM_AV>>>(out + QIJ_OFF, out + UV_OFF,
                                                        out + EST_OFF);

    k_clinear_tc<<<gl, 512, SMEM_GEMM>>>(out + EST_OFF, Wp, Wp + DxD, -1.0f, bp,
                                         out + OUT_OFF, cs2, 0, 0);
    k_clinear_tc<<<gl, 512, SMEM_GEMM>>>(out + EST_OFF, Wp + DxD, Wp, 1.0f, bp + DD,
                                         out + OUT_OFF + (size_t)NS * DD, cs2, 0, 0);
}

// round 17
// speedup vs baseline: 1.0822x; 1.0343x over previous
#include <cuda_runtime.h>
#include <math.h>
#include <stdint.h>

#define NS 2048
#define DD 256
#define BB 4
#define KC 32
#define KCP 36
#define NP2 72

// ---- output layout (floats), tuple order:
// est_eigenbasis (B,2,N,D), out (B,2,N,D), Q_ij (B,2,N,N), V_v (1,2,N,D),
// U_v (B,2,N,D), lambda_h (2,D,1)
static const size_t EST_OFF = 0;
static const size_t OUT_OFF = (size_t)BB * 2 * NS * DD;
static const size_t QIJ_OFF = OUT_OFF + (size_t)BB * 2 * NS * DD;
static const size_t VV_OFF  = QIJ_OFF + (size_t)BB * 2 * NS * NS;
static const size_t UV_OFF  = VV_OFF + (size_t)2 * NS * DD;
static const size_t LAM_OFF = UV_OFF + (size_t)BB * 2 * NS * DD;

// ---- scratch (device globals; no allocation allowed)
__device__ float g_ga, g_om, g_s, g_tau2;
__device__ __align__(16) float g_Qr[BB * NS * DD];
__device__ __align__(16) float g_Kr[BB * NS * DD];
__device__ float g_qn[BB * NS];
__device__ float g_kn[BB * NS];

__device__ __forceinline__ float neginf() { return __int_as_float(0xff800000); }

__device__ __forceinline__ uint32_t f2tf(float x) {
    uint32_t r;
    asm("cvt.rna.tf32.f32 %0, %1;" : "=r"(r) : "f"(x));
    return r;
}

__device__ __forceinline__ void mma_tf32(float* d, const uint32_t* a, const uint32_t* b) {
    asm volatile(
        "mma.sync.aligned.m16n8k8.row.col.f32.tf32.tf32.f32 "
        "{%0,%1,%2,%3}, {%4,%5,%6,%7}, {%8,%9}, {%0,%1,%2,%3};"
        : "+f"(d[0]), "+f"(d[1]), "+f"(d[2]), "+f"(d[3])
        : "r"(a[0]), "r"(a[1]), "r"(a[2]), "r"(a[3]), "r"(b[0]), "r"(b[1]));
}

// 512-thread GEMM fragment compute: block 128x128, 16 warps (4m x 4n),
// warp tile 32x32. A,B smem row-major [row][k], KCP-padded (conflict-free).
#define GEMM_COMPUTE2(AsB, BsB)                                                \
    _Pragma("unroll")                                                          \
    for (int kk = 0; kk < KC; kk += 8) {                                       \
        uint32_t af[2][4], bf[4][2];                                           \
        _Pragma("unroll")                                                      \
        for (int mt = 0; mt < 2; mt++) {                                       \
            int ab = (wm * 32 + mt * 16 + lr) * KCP + kk + lc;                 \
            af[mt][0] = (AsB)[ab];                                             \
            af[mt][1] = (AsB)[ab + 8 * KCP];                                   \
            af[mt][2] = (AsB)[ab + 4];                                         \
            af[mt][3] = (AsB)[ab + 8 * KCP + 4];                               \
        }                                                                      \
        _Pragma("unroll")                                                      \
        for (int nt = 0; nt < 4; nt++) {                                       \
            int bb2 = (wn * 32 + nt * 8 + lr) * KCP + kk + lc;                 \
            bf[nt][0] = (BsB)[bb2];                                            \
            bf[nt][1] = (BsB)[bb2 + 4];                                        \
        }                                                                      \
        _Pragma("unroll")                                                      \
        for (int mt = 0; mt < 2; mt++)                                         \
            _Pragma("unroll")                                                  \
            for (int nt = 0; nt < 4; nt++)                                     \
                mma_tf32(acc[mt][nt], af[mt], bf[nt]);                         \
    }

#define STS_TILE8(dst, reg)                                                    \
    {                                                                          \
        _Pragma("unroll")                                                      \
        for (int j = 0; j < 2; j++) {                                          \
            uint4 u;                                                           \
            u.x = f2tf((reg)[j].x); u.y = f2tf((reg)[j].y);                    \
            u.z = f2tf((reg)[j].z); u.w = f2tf((reg)[j].w);                    \
            *(uint4*)((dst) + 4 * j) = u;                                      \
        }                                                                      \
    }

// ============================================================================
__global__ void k_scalars(const float* __restrict__ lamOm,
                          const float* __restrict__ lamGa,
                          const float* __restrict__ lamC,
                          const float* __restrict__ tau,
                          const float* __restrict__ delta) {
    __shared__ float sga[8], som[8];
    int t = threadIdx.x;
    float c2 = lamC[t] * lamC[t];
    float ga = c2 * (lamGa[t] * lamGa[t] + 1e-5f);
    float om = c2 * (lamOm[t] * lamOm[t] + 1e-5f);
    for (int o = 16; o > 0; o >>= 1) {
        ga += __shfl_down_sync(0xffffffffu, ga, o);
        om += __shfl_down_sync(0xffffffffu, om, o);
    }
    if ((t & 31) == 0) { sga[t >> 5] = ga; som[t >> 5] = om; }
    __syncthreads();
    if (t == 0) {
        float a = 0.f, b = 0.f;
        for (int w = 0; w < 8; w++) { a += sga[w]; b += som[w]; }
        g_ga = a / 256.0f;
        g_om = b / 256.0f;
        g_s = 1.0f / (1.0f + expf(-delta[0]));
        g_tau2 = tau[0] * tau[0];
    }
}

// ============================================================================
// clinear (512 threads): C = Z0.Wa^T + sign*Z1.Wb^T + bias, K=512.
// Prefetch distance 2 + one barrier per stage (round-14 configuration).
// ============================================================================
#define CL_LOAD(dstA, dstB, s)                                                 \
    {                                                                          \
        const float* Asrc_ = ((s) < 8) ? Z1 : Z0;                              \
        const float* Bsrc_ = ((s) < 8) ? Wb : Wa;                              \
        int col_ = ((s) & 7) * 32 + aK;                                        \
        const float4* pa_ = (const float4*)(Asrc_ + (size_t)(m0 + aRow) * DD + col_); \
        const float4* pb_ = (const float4*)(Bsrc_ + (size_t)(n0 + aRow) * DD + col_); \
        (dstA)[0] = pa_[0]; (dstA)[1] = pa_[1];                                \
        (dstB)[0] = pb_[0]; (dstB)[1] = pb_[1];                                \
    }

#define CL_STAGE(kt, arX, brX, AsB, BsB)                                       \
    {                                                                          \
        STS_TILE8((AsB) + aRow * KCP + aK, arX);                               \
        STS_TILE8((BsB) + aRow * KCP + aK, brX);                               \
        __syncthreads();                                                       \
        if ((kt) + 2 < 16) CL_LOAD(arX, brX, (kt) + 2);                        \
        GEMM_COMPUTE2(AsB, BsB);                                               \
        if ((kt) == 7) {                                                       \
            _Pragma("unroll")                                                  \
            for (int mt = 0; mt < 2; mt++)                                     \
                _Pragma("unroll")                                              \
                for (int nt = 0; nt < 4; nt++)                                 \
                    _Pragma("unroll")                                          \
                    for (int q = 0; q < 4; q++) acc[mt][nt][q] *= sign;        \
        }                                                                      \
    }

__global__ __launch_bounds__(512) void k_clinear_tc(
    const float* __restrict__ Z, const float* __restrict__ Wa,
    const float* __restrict__ Wb, float sign, const float* __restrict__ bias,
    float* Cext, long cStride, int destSel, int scaleMode) {
    extern __shared__ uint32_t sm[];
    uint32_t* As0 = sm;
    uint32_t* As1 = sm + 128 * KCP;
    uint32_t* Bs0 = sm + 2 * 128 * KCP;
    uint32_t* Bs1 = sm + 3 * 128 * KCP;
    int b = blockIdx.z;
    const float* Z0 = Z + (size_t)b * 2 * NS * DD;
    const float* Z1 = Z0 + (size_t)NS * DD;
    int n0 = blockIdx.x * 128, m0 = blockIdx.y * 128;
    int t = threadIdx.x, wid = t >> 5, lane = t & 31;
    int wm = wid >> 2, wn = wid & 3, lr = lane >> 2, lc = lane & 3;
    int aRow = t >> 2, aK = (t & 3) * 8;

    float acc[2][4][4] = {};
    float4 ar0[2], br0[2], ar1[2], br1[2];

    CL_LOAD(ar0, br0, 0);
    CL_LOAD(ar1, br1, 1);

    #pragma unroll 1
    for (int kt = 0; kt < 16; kt += 2) {
        CL_STAGE(kt, ar0, br0, As0, Bs0);
        CL_STAGE(kt + 1, ar1, br1, As1, Bs1);
    }

    float* C; long cs;
    if (destSel == 1)      { C = g_Qr; cs = (long)NS * DD; }
    else if (destSel == 2) { C = g_Kr; cs = (long)NS * DD; }
    else                   { C = Cext; cs = cStride; }
    C += (size_t)b * cs;

    float scale = scaleMode ? (1.0f - g_s) : 1.0f;
    #pragma unroll
    for (int mt = 0; mt < 2; mt++) {
        #pragma unroll
        for (int nt = 0; nt < 4; nt++) {
            int col = n0 + wn * 32 + nt * 8 + lc * 2;
            float b0 = bias[col], b1 = bias[col + 1];
            int r0 = m0 + wm * 32 + mt * 16 + lr;
            float2 o0, o1;
            o0.x = (acc[mt][nt][0] + b0) * scale;
            o0.y = (acc[mt][nt][1] + b1) * scale;
            o1.x = (acc[mt][nt][2] + b0) * scale;
            o1.y = (acc[mt][nt][3] + b1) * scale;
            *(float2*)(C + (size_t)r0 * DD + col) = o0;
            *(float2*)(C + (size_t)(r0 + 8) * DD + col) = o1;
        }
    }
}

// ============================================================================
// Row norms, merged: blockIdx.y = 0 -> Q, 1 -> K
// ============================================================================
__global__ void k_norms2() {
    int which = blockIdx.y;
    const float* X = which ? g_Kr : g_Qr;
    float* out = which ? g_kn : g_qn;
    int warp = threadIdx.x >> 5, lane = threadIdx.x & 31;
    int row = blockIdx.x * 8 + warp;
    const float* p = X + (size_t)row * DD;
    float s = 0.f;
    #pragma unroll
    for (int l = 0; l < 8; l++) { float v = p[lane + l * 32]; s += v * v; }
    for (int o = 16; o > 0; o >>= 1) s += __shfl_down_sync(0xffffffffu, s, o);
    if (lane == 0) out[row] = s;
}

// ============================================================================
// Scores (512 threads): tile 128x128, bx<=by only. Prefetch 2, one sync/stage.
// ============================================================================
#define SC_LOAD(dstA, dstB, s)                                                 \
    {                                                                          \
        int col_ = (s) * 32 + aK;                                              \
        const float4* pa_ = (const float4*)(Q + (size_t)(i0 + aRow) * DD + col_); \
        const float4* pb_ = (const float4*)(K + (size_t)(j0 + aRow) * DD + col_); \
        (dstA)[0] = pa_[0]; (dstA)[1] = pa_[1];                                \
        (dstB)[0] = pb_[0]; (dstB)[1] = pb_[1];                                \
    }

#define SC_STAGE(kt, arX, brX, AsB, BsB)                                       \
    {                                                                          \
        STS_TILE8((AsB) + aRow * KCP + aK, arX);                               \
        STS_TILE8((BsB) + aRow * KCP + aK, brX);                               \
        __syncthreads();                                                       \
        if ((kt) + 2 < 8) SC_LOAD(arX, brX, (kt) + 2);                         \
        GEMM_COMPUTE2(AsB, BsB);                                               \
    }

__global__ __launch_bounds__(512) void k_scores_tc(float* __restrict__ Aout) {
    if (blockIdx.x > blockIdx.y) return;
    extern __shared__ uint32_t sm[];
    uint32_t* As0 = sm;
    uint32_t* As1 = sm + 128 * KCP;
    uint32_t* Bs0 = sm + 2 * 128 * KCP;
    uint32_t* Bs1 = sm + 3 * 128 * KCP;
    int b = blockIdx.z;
    int j0 = blockIdx.x * 128, i0 = blockIdx.y * 128;
    float* C = Aout + (size_t)b * 2 * NS * NS;
    const float* Q = g_Qr + (size_t)b * NS * DD;
    const float* K = g_Kr + (size_t)b * NS * DD;
    int t = threadIdx.x, wid = t >> 5, lane = t & 31;
    int wm = wid >> 2, wn = wid & 3, lr = lane >> 2, lc = lane & 3;
    int aRow = t >> 2, aK = (t & 3) * 8;

    float acc[2][4][4] = {};
    float4 ar0[2], br0[2], ar1[2], br1[2];

    SC_LOAD(ar0, br0, 0);
    SC_LOAD(ar1, br1, 1);

    #pragma unroll 1
    for (int kt = 0; kt < 8; kt += 2) {
        SC_STAGE(kt, ar0, br0, As0, Bs0);
        SC_STAGE(kt + 1, ar1, br1, As1, Bs1);
    }

    float tau2 = g_tau2, ga = g_ga, om = g_om;
    #pragma unroll
    for (int mt = 0; mt < 2; mt++) {
        #pragma unroll
        for (int half = 0; half < 2; half++) {
            int gi = i0 + wm * 32 + mt * 16 + lr + half * 8;
            float qn = g_qn[b * NS + gi];
            float* crow = C + (size_t)gi * NS;
            #pragma unroll
            for (int nt = 0; nt < 4; nt++) {
                int gj = j0 + wn * 32 + nt * 8 + lc * 2;
                float a0 = acc[mt][nt][half * 2 + 0];
                float a1 = acc[mt][nt][half * 2 + 1];
                if (gj + 1 <= gi) {
                    float2 o;
                    float r0 = qn + g_kn[b * NS + gj] - 2.0f * a0;
                    float r1 = qn + g_kn[b * NS + gj + 1] - 2.0f * a1;
                    o.x = -tau2 * __logf(ga + om * (0.01f * (float)(gi - gj)) + r0);
                    o.y = -tau2 * __logf(ga + om * (0.01f * (float)(gi - gj - 1)) + r1);
                    *(float2*)(crow + gj) = o;
                } else if (gj <= gi) {
                    float r0 = qn + g_kn[b * NS + gj] - 2.0f * a0;
                    crow[gj] = -tau2 * __logf(ga + om * (0.01f * (float)(gi - gj)) + r0);
                }
            }
        }
    }
}

// ============================================================================
// Row softmax (512 threads): reads only j<=i, writes full row.
// ============================================================================
__global__ __launch_bounds__(512) void k_softmax(float* __restrict__ A) {
    __shared__ float buf[NS];
    __shared__ float red[16];
    __shared__ float red2[16];
    int r = blockIdx.x;
    int b = r >> 11, i = r & 2047;
    float* row = A + (size_t)b * 2 * NS * NS + (size_t)i * NS;
    int t = threadIdx.x;
    int L = i + 1;

    float m = neginf();
    #pragma unroll
    for (int l = 0; l < 4; l++) {
        int idx = t + l * 512;
        float v = (idx < L) ? row[idx] : neginf();
        buf[idx] = v;
        m = fmaxf(m, v);
    }
    for (int o = 16; o > 0; o >>= 1) m = fmaxf(m, __shfl_xor_sync(0xffffffffu, m, o));
    if ((t & 31) == 0) red[t >> 5] = m;
    __syncthreads();
    float M = red[0];
    #pragma unroll
    for (int w = 1; w < 16; w++) M = fmaxf(M, red[w]);

    float s = 0.f;
    #pragma unroll
    for (int l = 0; l < 4; l++) {
        int idx = t + l * 512;
        float e = (idx < L) ? __expf(buf[idx] - M) : 0.0f;
        buf[idx] = e;
        s += e;
    }
    for (int o = 16; o > 0; o >>= 1) s += __shfl_xor_sync(0xffffffffu, s, o);
    if ((t & 31) == 0) red2[t >> 5] = s;
    __syncthreads();
    float S = 0.f;
    #pragma unroll
    for (int w = 0; w < 16; w++) S += red2[w];
    float inv = 1.0f / S;
    #pragma unroll
    for (int l = 0; l < 4; l++) {
        int idx = t + l * 512;
        row[idx] = buf[idx] * inv;
    }
}

// ============================================================================
// est_real = (1-s)*V_r + s*(A @ V_r), paired-triangular, 512 THREADS:
// 16 warps of 16(M)x32(N) warp tiles over the 128x64 block tile
// (wm = wid>>1 in 0..7 m-strips, wn = wid&1 in 0..1 n-strips).
// One barrier per stage; same KC=32/KCP=36/NP2 layout and staging as r14.
// ============================================================================
__global__ __launch_bounds__(512) void k_av_est_tc(const float* __restrict__ Aout,
                                                   const float* __restrict__ Uv,
                                                   float* __restrict__ est) {
    extern __shared__ uint32_t sm[];
    uint32_t* As0 = sm;
    uint32_t* As1 = sm + 128 * KCP;
    uint32_t* Vs0 = sm + 2 * 128 * KCP;
    uint32_t* Vs1 = Vs0 + 32 * NP2;
    int b = blockIdx.z;
    int n0 = blockIdx.x * 64;
    int p = blockIdx.y;
    const float* A = Aout + (size_t)b * 2 * NS * NS;
    const float* V = Uv + (size_t)b * 2 * NS * DD;
    int t = threadIdx.x, wid = t >> 5, lane = t & 31;
    int wm = wid >> 1, wn = wid & 1, lr = lane >> 2, lc = lane & 3;
    int aRow = t >> 2, aK = (t & 3) * 8;       // A loader: 4 thr/row, 8 floats
    int vRow = t >> 4, vCol = (t & 15) * 4;    // V loader: 16 thr/row, 4 floats
    float s = g_s, oms = 1.0f - s;
    float* E = est + (size_t)b * 2 * NS * DD;

    #pragma unroll 1
    for (int hp = 0; hp < 2; hp++) {
        int tile = hp ? p : (15 - p);
        int i0 = tile * 128;
        int S = 4 * (tile + 1);

        float acc[4][4] = {};
        float4 ar[2], vr;
        {
            const float4* pa = (const float4*)(A + (size_t)(i0 + aRow) * NS + aK);
            ar[0] = pa[0]; ar[1] = pa[1];
            vr = *(const float4*)(V + (size_t)vRow * DD + n0 + vCol);
        }
        __syncthreads();  // protect shared buffers across hp passes
        #pragma unroll 1
        for (int kt = 0; kt < S; kt++) {
            uint32_t* AsB = (kt & 1) ? As1 : As0;
            uint32_t* VsB = (kt & 1) ? Vs1 : Vs0;
            STS_TILE8(AsB + aRow * KCP + aK, ar);
            {
                uint4 u;
                u.x = f2tf(vr.x); u.y = f2tf(vr.y);
                u.z = f2tf(vr.z); u.w = f2tf(vr.w);
                *(uint4*)(VsB + vRow * NP2 + vCol) = u;
            }
            __syncthreads();
            if (kt + 1 < S) {
                int k0 = (kt + 1) * 32;
                const float4* pa = (const float4*)(A + (size_t)(i0 + aRow) * NS + k0 + aK);
                ar[0] = pa[0]; ar[1] = pa[1];
                vr = *(const float4*)(V + (size_t)(k0 + vRow) * DD + n0 + vCol);
            }
            #pragma unroll
            for (int kk = 0; kk < KC; kk += 8) {
                uint32_t af[4], bf[4][2];
                {
                    int ab = (wm * 16 + lr) * KCP + kk + lc;
                    af[0] = AsB[ab];
                    af[1] = AsB[ab + 8 * KCP];
                    af[2] = AsB[ab + 4];
                    af[3] = AsB[ab + 8 * KCP + 4];
                }
                #pragma unroll
                for (int nt = 0; nt < 4; nt++) {
                    int nb = wn * 32 + nt * 8 + lr;
                    bf[nt][0] = VsB[(kk + lc) * NP2 + nb];
                    bf[nt][1] = VsB[(kk + lc + 4) * NP2 + nb];
                }
                #pragma unroll
                for (int nt = 0; nt < 4; nt++)
                    mma_tf32(acc[nt], af, bf[nt]);
            }
        }
        __syncthreads();

        #pragma unroll
        for (int half = 0; half < 2; half++) {
            int row = i0 + wm * 16 + lr + half * 8;
            #pragma unroll
            for (int nt = 0; nt < 4; nt++) {
                int col = n0 + wn * 32 + nt * 8 + lc * 2;
                float2 vv = *(const float2*)(V + (size_t)row * DD + col);
                float2 o;
                o.x = oms * vv.x + s * acc[nt][half * 2 + 0];
                o.y = oms * vv.y + s * acc[nt][half * 2 + 1];
                *(float2*)(E + (size_t)row * DD + col) = o;
            }
        }
    }
}

// ============================================================================
// One merged fill kernel for ALL constant output regions.
// ============================================================================
#define F4_ONES 131072UL
#define F4_VVI  131072UL
#define F4_UVI  (4UL * 131072UL)
#define F4_QIJ  (4UL * 1048576UL)
#define F4_LAM  128UL
#define F4_TOT  (F4_ONES + F4_VVI + F4_UVI + F4_QIJ + F4_LAM)

__global__ void k_fill_all(float* __restrict__ out) {
    const float4 Z = {0.f, 0.f, 0.f, 0.f};
    const float4 O = {1.f, 1.f, 1.f, 1.f};
    size_t i = (size_t)blockIdx.x * blockDim.x + threadIdx.x;
    size_t stride = (size_t)gridDim.x * blockDim.x;
    for (; i < F4_TOT; i += stride) {
        size_t j = i;
        if (j < F4_ONES) {
            ((float4*)(out + VV_OFF))[j] = O;
            continue;
        }
        j -= F4_ONES;
        float4* dst;
        if (j < F4_VVI) {
            dst = (float4*)(out + VV_OFF + (size_t)NS * DD) + j;
        } else {
            j -= F4_VVI;
            if (j < F4_UVI) {
                size_t b = j >> 17, o = j & 131071UL;
                dst = (float4*)(out + UV_OFF + (2 * b + 1) * (size_t)NS * DD) + o;
            } else {
                j -= F4_UVI;
                if (j < F4_QIJ) {
                    size_t b = j >> 20, o = j & 1048575UL;
                    dst = (float4*)(out + QIJ_OFF + (2 * b + 1) * (size_t)NS * NS) + o;
                } else {
                    j -= F4_QIJ;
                    dst = (float4*)(out + LAM_OFF) + j;
                }
            }
        }
        *dst = Z;
    }
}

// ============================================================================
extern "C" void kernel_launch(void* const* d_in, const int* in_sizes, int n_in,
                              void* d_out, int out_size) {
    const float* Zq    = (const float*)d_in[0];
    const float* Zk    = (const float*)d_in[1];
    const float* Zv    = (const float*)d_in[2];
    const float* Wq    = (const float*)d_in[4];
    const float* bq    = (const float*)d_in[5];
    const float* Wk    = (const float*)d_in[6];
    const float* bk    = (const float*)d_in[7];
    const float* Wv    = (const float*)d_in[8];
    const float* bv    = (const float*)d_in[9];
    const float* Wp    = (const float*)d_in[10];
    const float* bp    = (const float*)d_in[11];
    const float* lamOm = (const float*)d_in[13];
    const float* lamGa = (const float*)d_in[14];
    const float* tau   = (const float*)d_in[15];
    const float* delta = (const float*)d_in[16];
    const float* lamC  = (const float*)d_in[17];

    float* out = (float*)d_out;
    const long DxD = (long)DD * DD;
    const long cs2 = (long)2 * NS * DD;

    const int SMEM_GEMM = 4 * 128 * KCP * 4;                    // 73728
    const int SMEM_AV   = (2 * 128 * KCP + 2 * 32 * NP2) * 4;   // 55296
    cudaFuncSetAttribute(k_clinear_tc, cudaFuncAttributeMaxDynamicSharedMemorySize, SMEM_GEMM);
    cudaFuncSetAttribute(k_scores_tc,  cudaFuncAttributeMaxDynamicSharedMemorySize, SMEM_GEMM);
    cudaFuncSetAttribute(k_av_est_tc,  cudaFuncAttributeMaxDynamicSharedMemorySize, SMEM_AV);

    k_scalars<<<1, 256>>>(lamOm, lamGa, lamC, tau, delta);

    // merged fills (independent; fire early)
    k_fill_all<<<2368, 256>>>(out);

    dim3 gl(DD / 128, NS / 128, BB);  // (2, 16, 4)
    k_clinear_tc<<<gl, 512, SMEM_GEMM>>>(Zq, Wq, Wq + DxD, -1.0f, bq, nullptr, 0, 1, 0);
    k_clinear_tc<<<gl, 512, SMEM_GEMM>>>(Zk, Wk, Wk + DxD, -1.0f, bk, nullptr, 0, 2, 0);
    k_clinear_tc<<<gl, 512, SMEM_GEMM>>>(Zv, Wv, Wv + DxD, -1.0f, bv, out + UV_OFF, cs2, 0, 0);
    k_clinear_tc<<<gl, 512, SMEM_GEMM>>>(Zv, Wv + DxD, Wv, 1.0f, bv + DD,
                                         out + EST_OFF + (size_t)NS * DD, cs2, 0, 1);

    k_norms2<<<dim3(BB * NS / 8, 2), 256>>>();

    k_scores_tc<<<dim3(NS / 128, NS / 128, BB), 512, SMEM_GEMM>>>(out + QIJ_OFF);
    k_softmax<<<BB * NS, 512>>>(out + QIJ_OFF);

    k_av_est_tc<<<dim3(DD / 64, 8, BB), 512, SMEM_AV>>>(out + QIJ_OFF, out + UV_OFF,
                                                        out + EST_OFF);

    k_clinear_tc<<<gl, 512, SMEM_GEMM>>>(out + EST_OFF, Wp, Wp + DxD, -1.0f, bp,
                                         out + OUT_OFF, cs2, 0, 0);
    k_clinear_tc<<<gl, 512, SMEM_GEMM>>>(out + EST_OFF, Wp + DxD, Wp, 1.0f, bp + DD,
                                         out + OUT_OFF + (size_t)NS * DD, cs2, 0, 0);
}